// round 8
// baseline (speedup 1.0000x reference)
#include <cuda_runtime.h>
#include <cuda_bf16.h>

// ---------------------------------------------------------------------------
// SurvivalGNN: 2-layer GCN (N=50000, D=128, E=800000) + 2 linear heads.
//   hs[i]  = (act(in) @ W)[i] * dinv[i]    (GEMM, packed fma.rn.f32x2,
//                                           x duplicated in smem -> no packs)
//   agg[i] = hs[i] + sum_{e: dst=i} hs[src] (CSR gather, warp per node)
// ---------------------------------------------------------------------------

#define NMAX 50000
#define EMAX 800000
#define D 128

typedef unsigned long long u64;

__device__ int   g_degi  [NMAX];
__device__ int   g_rowptr[NMAX + 1];
__device__ int   g_fill  [NMAX];
__device__ int   g_bsum  [256];
__device__ int   g_csr   [EMAX];
__device__ float g_dinv  [NMAX];
__device__ float g_hs    [NMAX * D];
__device__ float g_agg   [NMAX * D];

#define FMA_F32X2(d, a, b, c) \
    asm("fma.rn.f32x2 %0, %1, %2, %3;" : "=l"(d) : "l"(a), "l"(b), "l"(c))
#define PACK_F32X2(d, lo, hi) \
    asm("mov.b64 %0, {%1, %2};" : "=l"(d) : "f"(lo), "f"(hi))
#define UNPACK_F32X2(lo, hi, in) \
    asm("mov.b64 {%0, %1}, %2;" : "=f"(lo), "=f"(hi) : "l"(in))

// ---- degree / dinv / CSR -------------------------------------------------
__global__ void k_zero(int n) {
    int i = blockIdx.x * blockDim.x + threadIdx.x;
    if (i < n) g_degi[i] = 0;
}
__global__ void k_count_deg(const int* __restrict__ ei, int E) {
    int e = blockIdx.x * blockDim.x + threadIdx.x;
    if (e < E) atomicAdd(&g_degi[ei[E + e]], 1);       // dst = ei[1][e]
}
__global__ void k_scan1(int n) {             // per-block scan + dinv
    __shared__ int s[256];
    int t = threadIdx.x, i = blockIdx.x * 256 + t;
    int v = (i < n) ? g_degi[i] : 0;
    if (i < n) g_dinv[i] = rsqrtf((float)v + 1.0f);    // +1 self loop
    s[t] = v; __syncthreads();
    #pragma unroll
    for (int off = 1; off < 256; off <<= 1) {
        int a = (t >= off) ? s[t - off] : 0;
        __syncthreads(); s[t] += a; __syncthreads();
    }
    if (i < n) g_rowptr[i] = s[t] - v;
    if (t == 255) g_bsum[blockIdx.x] = s[255];
}
// per-block: reduce bsum[0..bid) locally, apply, init fill
__global__ void k_scan3(int n, int E, int nb) {
    __shared__ int s[256];
    int t = threadIdx.x, bid = blockIdx.x;
    s[t] = (t < bid && t < nb) ? g_bsum[t] : 0;
    __syncthreads();
    #pragma unroll
    for (int off = 128; off; off >>= 1) {
        if (t < off) s[t] += s[t + off];
        __syncthreads();
    }
    int off0 = s[0];
    int i = bid * 256 + t;
    if (i < n) {
        int r = g_rowptr[i] + off0;
        g_rowptr[i] = r;
        g_fill[i]   = r;
        if (i == 0) g_rowptr[n] = E;
    }
}
__global__ void k_scatter(const int* __restrict__ ei, int E) {
    int e = blockIdx.x * blockDim.x + threadIdx.x;
    if (e < E) {
        int pos = atomicAdd(&g_fill[ei[E + e]], 1);
        g_csr[pos] = ei[e];
    }
}

// ---- GEMM mainloop: acc = sx @ W via f32x2, x pre-duplicated in smem -----
// 64 rows/block, 8 rows/warp, lane owns cols [4*lane, 4*lane+4).
__device__ __forceinline__ void gemm_main(const u64 (*sxd)[D],
                                          const float* __restrict__ W,
                                          float* __restrict__ out, int base, int n)
{
    int t = threadIdx.x, warp = t >> 5, lane = t & 31;
    int r0 = warp * 8;
    u64 acc[8][2];
    #pragma unroll
    for (int r = 0; r < 8; r++) { acc[r][0] = 0ull; acc[r][1] = 0ull; }

    const float* Wp = W + lane * 4;
    #pragma unroll 4
    for (int k = 0; k < D; k++) {
        ulonglong2 w2 = *(const ulonglong2*)(Wp + k * D);
        #pragma unroll
        for (int r = 0; r < 8; r++) {
            u64 xv2 = sxd[r0 + r][k];                  // (x, x) broadcast
            FMA_F32X2(acc[r][0], xv2, w2.x, acc[r][0]);
            FMA_F32X2(acc[r][1], xv2, w2.y, acc[r][1]);
        }
    }
    #pragma unroll
    for (int r = 0; r < 8; r++) {
        int row = base + r0 + r;
        if (row < n) {
            float di = g_dinv[row];
            float4 o; float a0,a1,a2,a3;
            UNPACK_F32X2(a0, a1, acc[r][0]);
            UNPACK_F32X2(a2, a3, acc[r][1]);
            o.x = a0 * di; o.y = a1 * di; o.z = a2 * di; o.w = a3 * di;
            *(float4*)(out + (size_t)row * D + lane * 4) = o;
        }
    }
}

// ---- layer 1 GEMM: g_hs = (x @ W1) * dinv --------------------------------
__global__ void __launch_bounds__(256)
k_gemm1(const float* __restrict__ in, const float* __restrict__ W, int n)
{
    extern __shared__ u64 sxd[];                       // [64][D] duplicated
    u64 (*sx)[D] = (u64(*)[D])sxd;
    int t = threadIdx.x;
    int base = blockIdx.x * 64;
    #pragma unroll
    for (int j = 0; j < 8; j++) {
        int f = j * 256 + t;
        int r = f >> 5, c = f & 31;
        int row = base + r;
        float4 v = make_float4(0.f,0.f,0.f,0.f);
        if (row < n) v = *(const float4*)(in + (size_t)row * D + c * 4);
        ulonglong2 d0, d1;
        PACK_F32X2(d0.x, v.x, v.x); PACK_F32X2(d0.y, v.y, v.y);
        PACK_F32X2(d1.x, v.z, v.z); PACK_F32X2(d1.y, v.w, v.w);
        *(ulonglong2*)&sx[r][c * 4]     = d0;
        *(ulonglong2*)&sx[r][c * 4 + 2] = d1;
    }
    __syncthreads();
    gemm_main(sx, W, g_hs, base, n);
}

// ---- layer 2 GEMM: g_agg holds relu-input pre-activation ------------------
// loads agg, applies relu(dinv*agg + b1), duplicates into smem, GEMM -> g_hs
__global__ void __launch_bounds__(256)
k_gemm2(const float* __restrict__ b1, const float* __restrict__ W, int n)
{
    extern __shared__ u64 sxd[];
    u64 (*sx)[D] = (u64(*)[D])sxd;
    int t = threadIdx.x;
    int base = blockIdx.x * 64;
    #pragma unroll
    for (int j = 0; j < 8; j++) {
        int f = j * 256 + t;
        int r = f >> 5, c = f & 31;
        int row = base + r;
        float4 v = make_float4(0.f,0.f,0.f,0.f);
        if (row < n) {
            float  di = g_dinv[row];
            float4 a  = *(const float4*)(g_agg + (size_t)row * D + c * 4);
            float4 b  = *(const float4*)(b1 + c * 4);
            v.x = fmaxf(fmaf(di, a.x, b.x), 0.0f);
            v.y = fmaxf(fmaf(di, a.y, b.y), 0.0f);
            v.z = fmaxf(fmaf(di, a.z, b.z), 0.0f);
            v.w = fmaxf(fmaf(di, a.w, b.w), 0.0f);
        }
        ulonglong2 d0, d1;
        PACK_F32X2(d0.x, v.x, v.x); PACK_F32X2(d0.y, v.y, v.y);
        PACK_F32X2(d1.x, v.z, v.z); PACK_F32X2(d1.y, v.w, v.w);
        *(ulonglong2*)&sx[r][c * 4]     = d0;
        *(ulonglong2*)&sx[r][c * 4 + 2] = d1;
    }
    __syncthreads();
    gemm_main(sx, W, g_hs, base, n);                   // ping-pong -> g_hs
}

// ---- aggregation: agg[i] = hs[i] + sum_nbr hs[src] (warp per node) -------
__global__ void __launch_bounds__(256)
k_agg(int n)
{
    int w    = (blockIdx.x * blockDim.x + threadIdx.x) >> 5;
    int lane = threadIdx.x & 31;
    if (w >= n) return;

    size_t o = (size_t)w * D + lane * 4;
    float4 acc = *(const float4*)(g_hs + o);           // self loop
    int e = g_rowptr[w], end = g_rowptr[w + 1];
    for (; e + 3 < end; e += 4) {
        int s0 = g_csr[e], s1 = g_csr[e+1], s2 = g_csr[e+2], s3 = g_csr[e+3];
        float4 v0 = *(const float4*)(g_hs + (size_t)s0 * D + lane * 4);
        float4 v1 = *(const float4*)(g_hs + (size_t)s1 * D + lane * 4);
        float4 v2 = *(const float4*)(g_hs + (size_t)s2 * D + lane * 4);
        float4 v3 = *(const float4*)(g_hs + (size_t)s3 * D + lane * 4);
        acc.x += (v0.x + v1.x) + (v2.x + v3.x);
        acc.y += (v0.y + v1.y) + (v2.y + v3.y);
        acc.z += (v0.z + v1.z) + (v2.z + v3.z);
        acc.w += (v0.w + v1.w) + (v2.w + v3.w);
    }
    for (; e < end; e++) {
        int s0 = g_csr[e];
        float4 v0 = *(const float4*)(g_hs + (size_t)s0 * D + lane * 4);
        acc.x += v0.x; acc.y += v0.y; acc.z += v0.z; acc.w += v0.w;
    }
    *(float4*)(g_agg + o) = acc;
}

// ---- final aggregation (over g_hs = layer-2 messages) + heads ------------
__global__ void __launch_bounds__(256)
k_agg_heads(const float* __restrict__ b2,
            const float* __restrict__ Wt, const float* __restrict__ bt,
            const float* __restrict__ We, const float* __restrict__ be,
            float* __restrict__ out, int n)
{
    int w    = (blockIdx.x * blockDim.x + threadIdx.x) >> 5;
    int lane = threadIdx.x & 31;
    if (w >= n) return;

    size_t o = (size_t)w * D + lane * 4;
    float4 acc = *(const float4*)(g_hs + o);           // self loop
    int e = g_rowptr[w], end = g_rowptr[w + 1];
    for (; e + 3 < end; e += 4) {
        int s0 = g_csr[e], s1 = g_csr[e+1], s2 = g_csr[e+2], s3 = g_csr[e+3];
        float4 v0 = *(const float4*)(g_hs + (size_t)s0 * D + lane * 4);
        float4 v1 = *(const float4*)(g_hs + (size_t)s1 * D + lane * 4);
        float4 v2 = *(const float4*)(g_hs + (size_t)s2 * D + lane * 4);
        float4 v3 = *(const float4*)(g_hs + (size_t)s3 * D + lane * 4);
        acc.x += (v0.x + v1.x) + (v2.x + v3.x);
        acc.y += (v0.y + v1.y) + (v2.y + v3.y);
        acc.z += (v0.z + v1.z) + (v2.z + v3.z);
        acc.w += (v0.w + v1.w) + (v2.w + v3.w);
    }
    for (; e < end; e++) {
        int s0 = g_csr[e];
        float4 v0 = *(const float4*)(g_hs + (size_t)s0 * D + lane * 4);
        acc.x += v0.x; acc.y += v0.y; acc.z += v0.z; acc.w += v0.w;
    }

    float  di = g_dinv[w];
    float4 b  = *(const float4*)(b2 + lane * 4);
    float4 h;
    h.x = fmaxf(fmaf(di, acc.x, b.x), 0.0f);
    h.y = fmaxf(fmaf(di, acc.y, b.y), 0.0f);
    h.z = fmaxf(fmaf(di, acc.z, b.z), 0.0f);
    h.w = fmaxf(fmaf(di, acc.w, b.w), 0.0f);

    float4 wt = *(const float4*)(Wt + lane * 4);
    float4 we = *(const float4*)(We + lane * 4);
    float st = h.x*wt.x + h.y*wt.y + h.z*wt.z + h.w*wt.w;
    float ev = h.x*we.x + h.y*we.y + h.z*we.z + h.w*we.w;
    #pragma unroll
    for (int off = 16; off; off >>= 1) {
        st += __shfl_xor_sync(0xFFFFFFFFu, st, off);
        ev += __shfl_xor_sync(0xFFFFFFFFu, ev, off);
    }
    if (lane == 0) {
        out[w]     = st + bt[0];
        out[n + w] = ev + be[0];
    }
}

// ---------------------------------------------------------------------------
extern "C" void kernel_launch(void* const* d_in, const int* in_sizes, int n_in,
                              void* d_out, int out_size)
{
    const float* x   = (const float*)d_in[0];
    const int*   ei  = (const int*)  d_in[1];
    const float* W1  = (const float*)d_in[2];
    const float* b1  = (const float*)d_in[3];
    const float* W2  = (const float*)d_in[4];
    const float* b2  = (const float*)d_in[5];
    const float* Wt  = (const float*)d_in[6];
    const float* bt  = (const float*)d_in[7];
    const float* We  = (const float*)d_in[8];
    const float* be  = (const float*)d_in[9];
    float* out = (float*)d_out;

    int n = in_sizes[0] / D;       // 50000
    int E = in_sizes[1] / 2;       // 800000

    const int T = 256;
    const int SMEM = 64 * D * 8;   // 64 rows x 128 cols x 8B (duplicated) = 64KB
    int nb_n = (n + T - 1) / T;
    int nb_e = (E + T - 1) / T;
    int nb_g = (n + 63) / 64;
    int nb_w = (n + 7) / 8;

    cudaFuncSetAttribute(k_gemm1, cudaFuncAttributeMaxDynamicSharedMemorySize, SMEM);
    cudaFuncSetAttribute(k_gemm2, cudaFuncAttributeMaxDynamicSharedMemorySize, SMEM);

    // normalization + CSR
    k_zero     <<<nb_n, T>>>(n);
    k_count_deg<<<nb_e, T>>>(ei, E);
    k_scan1    <<<nb_n, T>>>(n);
    k_scan3    <<<nb_n, T>>>(n, E, nb_n);
    k_scatter  <<<nb_e, T>>>(ei, E);

    // layer 1: GEMM -> g_hs, aggregate -> g_agg
    k_gemm1<<<nb_g, T, SMEM>>>(x, W1, n);
    k_agg  <<<nb_w, T>>>(n);

    // layer 2: (relu transform + GEMM) -> g_hs, aggregate + heads -> out
    k_gemm2    <<<nb_g, T, SMEM>>>(b1, W2, n);
    k_agg_heads<<<nb_w, T>>>(b2, Wt, bt, We, be, out, n);
}

// round 10
// speedup vs baseline: 1.2518x; 1.2518x over previous
#include <cuda_runtime.h>
#include <cuda_bf16.h>

// ---------------------------------------------------------------------------
// SurvivalGNN: 2-layer GCN (N=50000, D=128, E=800000) + 2 linear heads.
//   hs[i]  = (act(in) @ W)[i] * dinv[i]     (scalar blocked GEMM, 8 rows/warp)
//   agg[i] = hs[i] + sum_{e: dst=i} hs[src] (CSR gather, warp/node, MLP=8)
// ---------------------------------------------------------------------------

#define NMAX 50000
#define EMAX 800000
#define D 128

__device__ int   g_degi  [NMAX];
__device__ int   g_rowptr[NMAX + 1];
__device__ int   g_fill  [NMAX];
__device__ int   g_bsum  [256];
__device__ int   g_csr   [EMAX];
__device__ float g_dinv  [NMAX];
__device__ float g_hs    [NMAX * D];
__device__ float g_agg   [NMAX * D];

// ---- degree / dinv / CSR -------------------------------------------------
__global__ void k_zero(int n) {
    int i = blockIdx.x * blockDim.x + threadIdx.x;
    if (i < n) g_degi[i] = 0;
}
__global__ void k_count_deg(const int* __restrict__ ei, int E) {
    int e = blockIdx.x * blockDim.x + threadIdx.x;
    if (e < E) atomicAdd(&g_degi[ei[E + e]], 1);       // dst = ei[1][e]
}
__global__ void k_scan1(int n) {             // per-block scan + dinv
    __shared__ int s[256];
    int t = threadIdx.x, i = blockIdx.x * 256 + t;
    int v = (i < n) ? g_degi[i] : 0;
    if (i < n) g_dinv[i] = rsqrtf((float)v + 1.0f);    // +1 self loop
    s[t] = v; __syncthreads();
    #pragma unroll
    for (int off = 1; off < 256; off <<= 1) {
        int a = (t >= off) ? s[t - off] : 0;
        __syncthreads(); s[t] += a; __syncthreads();
    }
    if (i < n) g_rowptr[i] = s[t] - v;
    if (t == 255) g_bsum[blockIdx.x] = s[255];
}
// per-block: reduce bsum[0..bid) locally, apply, init fill
__global__ void k_scan3(int n, int E, int nb) {
    __shared__ int s[256];
    int t = threadIdx.x, bid = blockIdx.x;
    s[t] = (t < bid && t < nb) ? g_bsum[t] : 0;
    __syncthreads();
    #pragma unroll
    for (int off = 128; off; off >>= 1) {
        if (t < off) s[t] += s[t + off];
        __syncthreads();
    }
    int off0 = s[0];
    int i = bid * 256 + t;
    if (i < n) {
        int r = g_rowptr[i] + off0;
        g_rowptr[i] = r;
        g_fill[i]   = r;
        if (i == 0) g_rowptr[n] = E;
    }
}
__global__ void k_scatter(const int* __restrict__ ei, int E) {
    int e = blockIdx.x * blockDim.x + threadIdx.x;
    if (e < E) {
        int pos = atomicAdd(&g_fill[ei[E + e]], 1);
        g_csr[pos] = ei[e];
    }
}

// ---- scalar GEMM mainloop (R3-proven): 64 rows/block, 8 rows/warp --------
__device__ __forceinline__ void gemm_main(const float (*sx)[D],
                                          const float* __restrict__ W,
                                          float* __restrict__ out, int base, int n)
{
    int t = threadIdx.x, warp = t >> 5, lane = t & 31;
    int r0 = warp * 8;
    float4 acc[8];
    #pragma unroll
    for (int r = 0; r < 8; r++) acc[r] = make_float4(0.f, 0.f, 0.f, 0.f);

    const float* Wp = W + lane * 4;
    #pragma unroll 4
    for (int k = 0; k < D; k++) {
        float4 w = *(const float4*)(Wp + k * D);
        #pragma unroll
        for (int r = 0; r < 8; r++) {
            float xv = sx[r0 + r][k];
            acc[r].x = fmaf(xv, w.x, acc[r].x);
            acc[r].y = fmaf(xv, w.y, acc[r].y);
            acc[r].z = fmaf(xv, w.z, acc[r].z);
            acc[r].w = fmaf(xv, w.w, acc[r].w);
        }
    }
    #pragma unroll
    for (int r = 0; r < 8; r++) {
        int row = base + r0 + r;
        if (row < n) {
            float di = g_dinv[row];
            float4 a = acc[r];
            a.x *= di; a.y *= di; a.z *= di; a.w *= di;
            *(float4*)(out + (size_t)row * D + lane * 4) = a;
        }
    }
}

// ---- layer 1 GEMM: g_hs = (x @ W1) * dinv --------------------------------
__global__ void __launch_bounds__(256)
k_gemm1(const float* __restrict__ in, const float* __restrict__ W, int n)
{
    __shared__ float sx[64][D];
    int t = threadIdx.x;
    int base = blockIdx.x * 64;
    #pragma unroll
    for (int j = 0; j < 8; j++) {
        int f = j * 256 + t;
        int r = f >> 5, c = f & 31;
        int row = base + r;
        if (row < n)
            *(float4*)&sx[r][c * 4] = *(const float4*)(in + (size_t)row * D + c * 4);
    }
    __syncthreads();
    gemm_main(sx, W, g_hs, base, n);
}

// ---- layer 2 GEMM: reads g_agg, applies relu(dinv*agg+b1), -> g_hs -------
__global__ void __launch_bounds__(256)
k_gemm2(const float* __restrict__ b1, const float* __restrict__ W, int n)
{
    __shared__ float sx[64][D];
    int t = threadIdx.x;
    int base = blockIdx.x * 64;
    #pragma unroll
    for (int j = 0; j < 8; j++) {
        int f = j * 256 + t;
        int r = f >> 5, c = f & 31;
        int row = base + r;
        if (row < n) {
            float  di = g_dinv[row];
            float4 a  = *(const float4*)(g_agg + (size_t)row * D + c * 4);
            float4 b  = *(const float4*)(b1 + c * 4);
            float4 v;
            v.x = fmaxf(fmaf(di, a.x, b.x), 0.0f);
            v.y = fmaxf(fmaf(di, a.y, b.y), 0.0f);
            v.z = fmaxf(fmaf(di, a.z, b.z), 0.0f);
            v.w = fmaxf(fmaf(di, a.w, b.w), 0.0f);
            *(float4*)&sx[r][c * 4] = v;
        }
    }
    __syncthreads();
    gemm_main(sx, W, g_hs, base, n);                   // ping-pong -> g_hs
}

// ---- gather body: acc += sum over csr[e..end) of g_hs rows, MLP=8 --------
__device__ __forceinline__ float4 gather_rows(float4 acc, int e, int end, int lane)
{
    for (; e + 7 < end; e += 8) {
        int s0 = g_csr[e],   s1 = g_csr[e+1], s2 = g_csr[e+2], s3 = g_csr[e+3];
        int s4 = g_csr[e+4], s5 = g_csr[e+5], s6 = g_csr[e+6], s7 = g_csr[e+7];
        float4 v0 = *(const float4*)(g_hs + (size_t)s0 * D + lane * 4);
        float4 v1 = *(const float4*)(g_hs + (size_t)s1 * D + lane * 4);
        float4 v2 = *(const float4*)(g_hs + (size_t)s2 * D + lane * 4);
        float4 v3 = *(const float4*)(g_hs + (size_t)s3 * D + lane * 4);
        float4 v4 = *(const float4*)(g_hs + (size_t)s4 * D + lane * 4);
        float4 v5 = *(const float4*)(g_hs + (size_t)s5 * D + lane * 4);
        float4 v6 = *(const float4*)(g_hs + (size_t)s6 * D + lane * 4);
        float4 v7 = *(const float4*)(g_hs + (size_t)s7 * D + lane * 4);
        acc.x += ((v0.x + v1.x) + (v2.x + v3.x)) + ((v4.x + v5.x) + (v6.x + v7.x));
        acc.y += ((v0.y + v1.y) + (v2.y + v3.y)) + ((v4.y + v5.y) + (v6.y + v7.y));
        acc.z += ((v0.z + v1.z) + (v2.z + v3.z)) + ((v4.z + v5.z) + (v6.z + v7.z));
        acc.w += ((v0.w + v1.w) + (v2.w + v3.w)) + ((v4.w + v5.w) + (v6.w + v7.w));
    }
    for (; e + 1 < end; e += 2) {
        int s0 = g_csr[e], s1 = g_csr[e+1];
        float4 v0 = *(const float4*)(g_hs + (size_t)s0 * D + lane * 4);
        float4 v1 = *(const float4*)(g_hs + (size_t)s1 * D + lane * 4);
        acc.x += v0.x + v1.x; acc.y += v0.y + v1.y;
        acc.z += v0.z + v1.z; acc.w += v0.w + v1.w;
    }
    if (e < end) {
        int s0 = g_csr[e];
        float4 v0 = *(const float4*)(g_hs + (size_t)s0 * D + lane * 4);
        acc.x += v0.x; acc.y += v0.y; acc.z += v0.z; acc.w += v0.w;
    }
    return acc;
}

// ---- aggregation: g_agg[i] = g_hs[i] + sum_nbr g_hs[src] -----------------
__global__ void __launch_bounds__(256)
k_agg(int n)
{
    int w    = (blockIdx.x * blockDim.x + threadIdx.x) >> 5;
    int lane = threadIdx.x & 31;
    if (w >= n) return;
    size_t o = (size_t)w * D + lane * 4;
    float4 acc = *(const float4*)(g_hs + o);           // self loop
    acc = gather_rows(acc, g_rowptr[w], g_rowptr[w + 1], lane);
    *(float4*)(g_agg + o) = acc;
}

// ---- final aggregation (over g_hs = layer-2 messages) + heads ------------
__global__ void __launch_bounds__(256)
k_agg_heads(const float* __restrict__ b2,
            const float* __restrict__ Wt, const float* __restrict__ bt,
            const float* __restrict__ We, const float* __restrict__ be,
            float* __restrict__ out, int n)
{
    int w    = (blockIdx.x * blockDim.x + threadIdx.x) >> 5;
    int lane = threadIdx.x & 31;
    if (w >= n) return;

    size_t o = (size_t)w * D + lane * 4;
    float4 acc = *(const float4*)(g_hs + o);           // self loop
    acc = gather_rows(acc, g_rowptr[w], g_rowptr[w + 1], lane);

    float  di = g_dinv[w];
    float4 b  = *(const float4*)(b2 + lane * 4);
    float4 h;
    h.x = fmaxf(fmaf(di, acc.x, b.x), 0.0f);
    h.y = fmaxf(fmaf(di, acc.y, b.y), 0.0f);
    h.z = fmaxf(fmaf(di, acc.z, b.z), 0.0f);
    h.w = fmaxf(fmaf(di, acc.w, b.w), 0.0f);

    float4 wt = *(const float4*)(Wt + lane * 4);
    float4 we = *(const float4*)(We + lane * 4);
    float st = h.x*wt.x + h.y*wt.y + h.z*wt.z + h.w*wt.w;
    float ev = h.x*we.x + h.y*we.y + h.z*we.z + h.w*we.w;
    #pragma unroll
    for (int off = 16; off; off >>= 1) {
        st += __shfl_xor_sync(0xFFFFFFFFu, st, off);
        ev += __shfl_xor_sync(0xFFFFFFFFu, ev, off);
    }
    if (lane == 0) {
        out[w]     = st + bt[0];
        out[n + w] = ev + be[0];
    }
}

// ---------------------------------------------------------------------------
extern "C" void kernel_launch(void* const* d_in, const int* in_sizes, int n_in,
                              void* d_out, int out_size)
{
    const float* x   = (const float*)d_in[0];
    const int*   ei  = (const int*)  d_in[1];
    const float* W1  = (const float*)d_in[2];
    const float* b1  = (const float*)d_in[3];
    const float* W2  = (const float*)d_in[4];
    const float* b2  = (const float*)d_in[5];
    const float* Wt  = (const float*)d_in[6];
    const float* bt  = (const float*)d_in[7];
    const float* We  = (const float*)d_in[8];
    const float* be  = (const float*)d_in[9];
    float* out = (float*)d_out;

    int n = in_sizes[0] / D;       // 50000
    int E = in_sizes[1] / 2;       // 800000

    const int T = 256;
    int nb_n = (n + T - 1) / T;
    int nb_e = (E + T - 1) / T;
    int nb_g = (n + 63) / 64;
    int nb_w = (n + 7) / 8;

    // normalization + CSR
    k_zero     <<<nb_n, T>>>(n);
    k_count_deg<<<nb_e, T>>>(ei, E);
    k_scan1    <<<nb_n, T>>>(n);
    k_scan3    <<<nb_n, T>>>(n, E, nb_n);
    k_scatter  <<<nb_e, T>>>(ei, E);

    // layer 1: GEMM -> g_hs, aggregate -> g_agg
    k_gemm1<<<nb_g, T>>>(x, W1, n);
    k_agg  <<<nb_w, T>>>(n);

    // layer 2: (relu transform + GEMM) -> g_hs, aggregate + heads -> out
    k_gemm2    <<<nb_g, T>>>(b1, W2, n);
    k_agg_heads<<<nb_w, T>>>(b2, Wt, bt, We, be, out, n);
}